// round 7
// baseline (speedup 1.0000x reference)
#include <cuda_runtime.h>
#include <cstdint>

// ---------------------------------------------------------------------------
// Problem constants: B=1, T=256, D=512, H=8, DH=64
// proj layout: [t, 5*512]; chunks k1@0, k2@512, q@1024, v1@1536, v2@2048.
// ---------------------------------------------------------------------------
#define T 256
#define D 512
#define H 8
#define DH 64
#define SST 66   // smem stride for generic gemm
#define AST 68   // smem stride for attn kernel (16B-aligned rows)

// Packed fp32x2 FMA (sm_100+)
#define FMA2(acc, a, b) asm("fma.rn.f32x2 %0, %1, %2, %0;" : "+l"(acc) : "l"(a), "l"(b))
#define DUP2(dst, f)    asm("mov.b64 %0, {%1, %1};" : "=l"(dst) : "r"(__float_as_uint(f)))
static __device__ __forceinline__ float lo2(unsigned long long v) { return __uint_as_float((unsigned int)v); }
static __device__ __forceinline__ float hi2(unsigned long long v) { return __uint_as_float((unsigned int)(v >> 32)); }

struct __align__(16) F4P { unsigned long long lo, hi; };   // two f32x2 k-pairs

// 16x FFMA2 rank-1 update (generic gemm kernel, broadcast style)
#define RANK1_FMA2(ACC, AR, B0, B1, B2, B3)                         \
    do {                                                            \
        unsigned long long _a0 = (AR)[0], _a1 = (AR)[1];            \
        unsigned long long _a2 = (AR)[2], _a3 = (AR)[3];            \
        FMA2(ACC[0][0], _a0, B0); FMA2(ACC[0][1], _a0, B1);         \
        FMA2(ACC[0][2], _a0, B2); FMA2(ACC[0][3], _a0, B3);         \
        FMA2(ACC[1][0], _a1, B0); FMA2(ACC[1][1], _a1, B1);         \
        FMA2(ACC[1][2], _a1, B2); FMA2(ACC[1][3], _a1, B3);         \
        FMA2(ACC[2][0], _a2, B0); FMA2(ACC[2][1], _a2, B1);         \
        FMA2(ACC[2][2], _a2, B2); FMA2(ACC[2][3], _a2, B3);         \
        FMA2(ACC[3][0], _a3, B0); FMA2(ACC[3][1], _a3, B1);         \
        FMA2(ACC[3][2], _a3, B2); FMA2(ACC[3][3], _a3, B3);         \
    } while (0)

// Scratch (device globals — allocation-free rule)
__device__ float g_proj[T * 5 * D];
__device__ float g_K1W[H * T * DH * DH];
__device__ float g_Vq1[H * T * DH * DH];
__device__ float g_A2[H * T * T * DH];   // [h][q][p*64+c], unscaled
__device__ float g_spart[H * T * T];     // [h][p][q]
__device__ float g_rowinv[H * T];
__device__ float g_z[T * H * DH];

// ---------------------------------------------------------------------------
// Generic batched tiled GEMM (unchanged from round 6).
// ---------------------------------------------------------------------------
__global__ __launch_bounds__(128)
void gemm_kernel(const float* __restrict__ A, const float* __restrict__ Bm,
                 float* __restrict__ C,
                 int lda, int ldb, int ldc,
                 int M, int N, int K, int P,
                 long long aH, long long aP,
                 long long bH, long long bP,
                 long long cH, long long cP,
                 int transB,
                 const float* __restrict__ bias,
                 const float* __restrict__ rowscale, int rsH,
                 int mode, int ksplit)
{
    int bz = blockIdx.z;
    int b  = bz / ksplit;
    int kc = bz % ksplit;
    int h = b / P, p = b % P;
    A  += (long long)h * aH + (long long)p * aP;
    Bm += (long long)h * bH + (long long)p * bP;
    C  += (long long)h * cH + (long long)p * cP;

    int m0 = blockIdx.y * 64;
    int n0 = blockIdx.x * 64;

    int k_begin = 0, k_end = K;
    if (ksplit > 1) { int kchunk = K / ksplit; k_begin = kc * kchunk; k_end = k_begin + kchunk; }
    if (mode == 4) {
        long long lim = (long long)(m0 + 64) * 64;
        if (lim < k_end) k_end = (int)lim;
        if (k_begin >= k_end) return;
    }

    __shared__ float As[64][SST];
    __shared__ float Bs[64][SST];

    int tid = threadIdx.x;
    int ty = tid >> 4, tx = tid & 15;

    unsigned long long acc2[4][4];
    #pragma unroll
    for (int i = 0; i < 4; i++)
        #pragma unroll
        for (int j = 0; j < 4; j++) acc2[i][j] = 0ULL;

    for (int k0 = k_begin; k0 < k_end; k0 += 64) {
        #pragma unroll 8
        for (int i = tid; i < 4096; i += 128) {
            int r = i >> 6, kk = i & 63;
            As[kk][r] = A[(long long)(m0 + r) * lda + (k0 + kk)];
        }
        if (transB) {
            #pragma unroll 8
            for (int i = tid; i < 4096; i += 128) {
                int n = i >> 6, kk = i & 63;
                Bs[kk][n] = Bm[(long long)(n0 + n) * ldb + (k0 + kk)];
            }
        } else {
            #pragma unroll 8
            for (int i = tid; i < 4096; i += 128) {
                int kk = i >> 6, n = i & 63;
                Bs[kk][n] = Bm[(long long)(k0 + kk) * ldb + (n0 + n)];
            }
        }
        __syncthreads();

        #pragma unroll 16
        for (int kk = 0; kk < 64; kk++) {
            const unsigned long long* arow =
                reinterpret_cast<const unsigned long long*>(&As[kk][ty * 8]);
            unsigned long long b0, b1, b2, b3;
            DUP2(b0, Bs[kk][tx * 4 + 0]); DUP2(b1, Bs[kk][tx * 4 + 1]);
            DUP2(b2, Bs[kk][tx * 4 + 2]); DUP2(b3, Bs[kk][tx * 4 + 3]);
            RANK1_FMA2(acc2, arow, b0, b1, b2, b3);
        }
        __syncthreads();
    }

    int n = n0 + tx * 4;
    float4 bv4 = {0,0,0,0};
    if (bias) { bv4.x = bias[n]; bv4.y = bias[n+1]; bv4.z = bias[n+2]; bv4.w = bias[n+3]; }
    #pragma unroll
    for (int ip = 0; ip < 4; ip++) {
        #pragma unroll
        for (int half = 0; half < 2; half++) {
            int m = m0 + ty * 8 + ip * 2 + half;
            float scale = rowscale ? rowscale[h * rsH + m] : 1.0f;
            float4 v;
            v.x = (half ? hi2(acc2[ip][0]) : lo2(acc2[ip][0])) * scale + bv4.x;
            v.y = (half ? hi2(acc2[ip][1]) : lo2(acc2[ip][1])) * scale + bv4.y;
            v.z = (half ? hi2(acc2[ip][2]) : lo2(acc2[ip][2])) * scale + bv4.z;
            v.w = (half ? hi2(acc2[ip][3]) : lo2(acc2[ip][3])) * scale + bv4.w;
            if (ksplit > 1) {
                atomicAdd(&C[(long long)m * ldc + n + 0], v.x);
                atomicAdd(&C[(long long)m * ldc + n + 1], v.y);
                atomicAdd(&C[(long long)m * ldc + n + 2], v.z);
                atomicAdd(&C[(long long)m * ldc + n + 3], v.w);
            } else {
                *reinterpret_cast<float4*>(&C[(long long)m * ldc + n]) = v;
            }
        }
    }
}

// ---------------------------------------------------------------------------
// Dot-pair 64x64x64 GEMM step for the attn kernel:
//   acc[i][j] (f32x2 partial sums over k-parity) +=
//       A[(ty*4+i)][k] * B[(tx+16j)][k], k = 0..63
// A, B row-major with stride AST; LDS.128 feeds two k-pairs per load.
// ---------------------------------------------------------------------------
static __device__ __forceinline__ void gemm_dp(unsigned long long acc[4][4],
                                               const float* __restrict__ A,
                                               const float* __restrict__ B,
                                               int ty, int tx)
{
    #pragma unroll 8
    for (int kr = 0; kr < 16; kr++) {
        int k = kr * 4;
        F4P a0 = *reinterpret_cast<const F4P*>(&A[(ty * 4 + 0) * AST + k]);
        F4P a1 = *reinterpret_cast<const F4P*>(&A[(ty * 4 + 1) * AST + k]);
        F4P a2 = *reinterpret_cast<const F4P*>(&A[(ty * 4 + 2) * AST + k]);
        F4P a3 = *reinterpret_cast<const F4P*>(&A[(ty * 4 + 3) * AST + k]);
        F4P b0 = *reinterpret_cast<const F4P*>(&B[(tx +  0) * AST + k]);
        F4P b1 = *reinterpret_cast<const F4P*>(&B[(tx + 16) * AST + k]);
        F4P b2 = *reinterpret_cast<const F4P*>(&B[(tx + 32) * AST + k]);
        F4P b3 = *reinterpret_cast<const F4P*>(&B[(tx + 48) * AST + k]);
        FMA2(acc[0][0], a0.lo, b0.lo); FMA2(acc[0][0], a0.hi, b0.hi);
        FMA2(acc[0][1], a0.lo, b1.lo); FMA2(acc[0][1], a0.hi, b1.hi);
        FMA2(acc[0][2], a0.lo, b2.lo); FMA2(acc[0][2], a0.hi, b2.hi);
        FMA2(acc[0][3], a0.lo, b3.lo); FMA2(acc[0][3], a0.hi, b3.hi);
        FMA2(acc[1][0], a1.lo, b0.lo); FMA2(acc[1][0], a1.hi, b0.hi);
        FMA2(acc[1][1], a1.lo, b1.lo); FMA2(acc[1][1], a1.hi, b1.hi);
        FMA2(acc[1][2], a1.lo, b2.lo); FMA2(acc[1][2], a1.hi, b2.hi);
        FMA2(acc[1][3], a1.lo, b3.lo); FMA2(acc[1][3], a1.hi, b3.hi);
        FMA2(acc[2][0], a2.lo, b0.lo); FMA2(acc[2][0], a2.hi, b0.hi);
        FMA2(acc[2][1], a2.lo, b1.lo); FMA2(acc[2][1], a2.hi, b1.hi);
        FMA2(acc[2][2], a2.lo, b2.lo); FMA2(acc[2][2], a2.hi, b2.hi);
        FMA2(acc[2][3], a2.lo, b3.lo); FMA2(acc[2][3], a2.hi, b3.hi);
        FMA2(acc[3][0], a3.lo, b0.lo); FMA2(acc[3][0], a3.hi, b0.hi);
        FMA2(acc[3][1], a3.lo, b1.lo); FMA2(acc[3][1], a3.hi, b1.hi);
        FMA2(acc[3][2], a3.lo, b2.lo); FMA2(acc[3][2], a3.hi, b2.hi);
        FMA2(acc[3][3], a3.lo, b3.lo); FMA2(acc[3][3], a3.hi, b3.hi);
    }
}

// ---------------------------------------------------------------------------
// Fully fused attention inner (dot-pair microkernel, 256 threads):
// per (h, p, qtile):
//   Phase1: St[q][j] = sum_i q_h[q,i] * K1W[h][p][j,i]
//   Per t-tile tt <= qt:
//     e[q][t] = (q>=p && t<=q) ? exp(logit/64) : 0
//     A2acc[q][c] += sum_t e[q][t] * v2[t][c]
//   Epilogue: A2[h][q][p*64+c], s_part[h][p][q]
// Thread tile 4x4, cols interleaved (tx + 16j). All smem k-major, stride AST.
// ---------------------------------------------------------------------------
__global__ __launch_bounds__(256, 2)
void attn_kernel(const float* __restrict__ proj,
                 const float* __restrict__ k1w,
                 float* __restrict__ A2,
                 float* __restrict__ s_part)
{
    int qt = blockIdx.x;
    int p  = blockIdx.y;
    int h  = blockIdx.z;
    if (qt * 64 + 63 < p) return;

    extern __shared__ float sm_dyn[];
    float* Sa = sm_dyn;                 // [q][i] then St [q][j]
    float* Sb = sm_dyn + 64 * AST;      // K1W [j][i], then k2 [t][j]
    float* Se = sm_dyn + 2 * 64 * AST;  // e [q][t]
    float* Sv = sm_dyn + 3 * 64 * AST;  // v2^T [c][t]

    const float* qmat = proj + 2 * D + h * 64;           // [q][i], ld=5D
    const float* k2m  = proj + 1 * D + h * 64;           // [t][j], ld=5D
    const float* v2m  = proj + 4 * D + h * 64;           // [t][c], ld=5D
    const float* Bp   = k1w + ((long long)h * T + p) * (DH * DH);  // [j*64+i]

    int tid = threadIdx.x;
    int ty = tid >> 4, tx = tid & 15;
    int q0 = qt * 64;

    // ---- fill q tile and K1W tile (both already k-major; straight float4 copy)
    #pragma unroll
    for (int l = 0; l < 4; l++) {
        int i4 = tid + 256 * l;
        int r = i4 >> 4, c4 = (i4 & 15) * 4;
        *reinterpret_cast<float4*>(&Sa[r * AST + c4]) =
            *reinterpret_cast<const float4*>(&qmat[(long long)(q0 + r) * (5 * D) + c4]);
        *reinterpret_cast<float4*>(&Sb[r * AST + c4]) =
            *reinterpret_cast<const float4*>(&Bp[i4 * 4]);
    }
    __syncthreads();

    // ---- Phase 1: St = q @ K1W^T (contract i) ----
    unsigned long long st2[4][4];
    #pragma unroll
    for (int i = 0; i < 4; i++)
        #pragma unroll
        for (int j = 0; j < 4; j++) st2[i][j] = 0ULL;
    gemm_dp(st2, Sa, Sb, ty, tx);
    __syncthreads();                     // everyone done reading Sa/Sb

    // store St (finalized) into Sa, k-major [q][j]; conflict-free (tx fastest)
    #pragma unroll
    for (int i = 0; i < 4; i++)
        #pragma unroll
        for (int j = 0; j < 4; j++)
            Sa[(ty * 4 + i) * AST + tx + 16 * j] = lo2(st2[i][j]) + hi2(st2[i][j]);

    float srow[4] = {0.0f, 0.0f, 0.0f, 0.0f};
    unsigned long long accA[4][4];
    #pragma unroll
    for (int i = 0; i < 4; i++)
        #pragma unroll
        for (int j = 0; j < 4; j++) accA[i][j] = 0ULL;

    // ---- Phase 2 ----
    for (int tt = 0; tt <= qt; tt++) {
        int t0 = tt * 64;
        __syncthreads();                 // prev GEMM2 done with Sb/Sv; St visible (tt=0)

        #pragma unroll
        for (int l = 0; l < 4; l++) {
            int i4 = tid + 256 * l;
            int r = i4 >> 4, c4 = (i4 & 15) * 4;
            *reinterpret_cast<float4*>(&Sb[r * AST + c4]) =
                *reinterpret_cast<const float4*>(&k2m[(long long)(t0 + r) * (5 * D) + c4]);
            float4 v = *reinterpret_cast<const float4*>(&v2m[(long long)(t0 + r) * (5 * D) + c4]);
            Sv[(c4 + 0) * AST + r] = v.x;
            Sv[(c4 + 1) * AST + r] = v.y;
            Sv[(c4 + 2) * AST + r] = v.z;
            Sv[(c4 + 3) * AST + r] = v.w;
        }
        __syncthreads();

        // GEMM1: e = St @ k2^T (contract j)
        unsigned long long e2[4][4];
        #pragma unroll
        for (int i = 0; i < 4; i++)
            #pragma unroll
            for (int j = 0; j < 4; j++) e2[i][j] = 0ULL;
        gemm_dp(e2, Sa, Sb, ty, tx);

        // finalize + exp + mask -> Se[q][t] + row sums
        bool diag = (tt == qt);
        #pragma unroll
        for (int i = 0; i < 4; i++) {
            int q = q0 + ty * 4 + i;
            bool vr = (q >= p);
            float rs = 0.0f;
            #pragma unroll
            for (int j = 0; j < 4; j++) {
                int tg = t0 + tx + 16 * j;
                float x = lo2(e2[i][j]) + hi2(e2[i][j]);
                float e = (vr && (!diag || tg <= q)) ? __expf(x * 0.015625f) : 0.0f;
                rs += e;
                Se[(ty * 4 + i) * AST + tx + 16 * j] = e;
            }
            srow[i] += rs;
        }
        __syncthreads();

        // GEMM2: A2acc += e @ v2 (contract t)
        gemm_dp(accA, Se, Sv, ty, tx);
    }

    // ---- Epilogue: A2 tile + s_part ----
    #pragma unroll
    for (int i = 0; i < 4; i++) {
        int q = q0 + ty * 4 + i;
        float* dst = &A2[((long long)(h * T + q)) * (T * DH) + p * 64];
        #pragma unroll
        for (int j = 0; j < 4; j++)
            dst[tx + 16 * j] = lo2(accA[i][j]) + hi2(accA[i][j]);
    }

    #pragma unroll
    for (int i = 0; i < 4; i++) {
        float s = srow[i];
        s += __shfl_xor_sync(0xffffffffu, s, 1);
        s += __shfl_xor_sync(0xffffffffu, s, 2);
        s += __shfl_xor_sync(0xffffffffu, s, 4);
        s += __shfl_xor_sync(0xffffffffu, s, 8);
        if (tx == 0)
            s_part[((long long)(h * T + p)) * T + q0 + ty * 4 + i] = s;
    }
}

// ---------------------------------------------------------------------------
// rowinv[h,q] = 1 / sum_{p<=q} s_part[h][p][q]
// ---------------------------------------------------------------------------
__global__ void rowinv_kernel(const float* __restrict__ s_part,
                              float* __restrict__ rowinv)
{
    int q = blockIdx.x, h = blockIdx.y;
    int tid = threadIdx.x;    // 256, tid == p
    float s = (tid <= q) ? s_part[((long long)(h * T + tid)) * T + q] : 0.0f;
    __shared__ float sh[256];
    sh[tid] = s;
    __syncthreads();
    for (int o = 128; o > 0; o >>= 1) {
        if (tid < o) sh[tid] += sh[tid + o];
        __syncthreads();
    }
    if (tid == 0) rowinv[h * T + q] = 1.0f / sh[0];
}

// ---------------------------------------------------------------------------
static inline void launch_gemm(const float* A, long long aH, long long aP, int lda,
                               const float* B, long long bH, long long bP, int ldb,
                               float* C, long long cH, long long cP, int ldc,
                               int M, int N, int K, int P, int batch,
                               int transB, const float* bias,
                               const float* rowscale, int rsH,
                               int mode, int ksplit)
{
    dim3 grid(N / 64, M / 64, batch * ksplit);
    gemm_kernel<<<grid, 128>>>(A, B, C, lda, ldb, ldc, M, N, K, P,
                               aH, aP, bH, bP, cH, cP,
                               transB, bias, rowscale, rsH, mode, ksplit);
}

extern "C" void kernel_launch(void* const* d_in, const int* in_sizes, int n_in,
                              void* d_out, int out_size)
{
    const float* x    = (const float*)d_in[0];
    const float* Wk   = (const float*)d_in[1];
    const float* bk   = (const float*)d_in[2];
    const float* WKq  = (const float*)d_in[3];
    const float* WVq  = (const float*)d_in[4];
    const float* Wout = (const float*)d_in[5];
    const float* bout = (const float*)d_in[6];
    float* out = (float*)d_out;

    float *proj, *k1w, *vq1, *A2, *spart, *rinv, *z;
    cudaGetSymbolAddress((void**)&proj,  g_proj);
    cudaGetSymbolAddress((void**)&k1w,   g_K1W);
    cudaGetSymbolAddress((void**)&vq1,   g_Vq1);
    cudaGetSymbolAddress((void**)&A2,    g_A2);
    cudaGetSymbolAddress((void**)&spart, g_spart);
    cudaGetSymbolAddress((void**)&rinv,  g_rowinv);
    cudaGetSymbolAddress((void**)&z,     g_z);

    const long long HPJ = (long long)T * DH * DH;
    const long long A2H = (long long)T * T * DH;

    // 1) proj = x @ W_kkqvv + b
    launch_gemm(x, 0, 0, D, Wk, 0, 0, 5 * D, proj, 0, 0, 5 * D,
                T, 5 * D, D, 1, 1, 0, bk, nullptr, 0, 0, 1);

    // 2) K1W[h] = k1_h @ W_Kq[h]
    launch_gemm(proj + 0, 64, 0, 5 * D, WKq, (long long)DH * DH * DH, 0, DH * DH,
                k1w, HPJ, 0, DH * DH,
                T, DH * DH, DH, 1, H, 0, nullptr, nullptr, 0, 0, 1);

    // 3) Vq1[h] = v1_h @ W_Vq[h]
    launch_gemm(proj + 3 * D, 64, 0, 5 * D, WVq, (long long)DH * DH * DH, 0, DH * DH,
                vq1, HPJ, 0, DH * DH,
                T, DH * DH, DH, 1, H, 0, nullptr, nullptr, 0, 0, 1);

    // 4) fused attention inner: A2 (unscaled) + partial row sums
    {
        int smem_bytes = 4 * 64 * AST * sizeof(float);   // 69632
        cudaFuncSetAttribute(attn_kernel,
                             cudaFuncAttributeMaxDynamicSharedMemorySize, smem_bytes);
        dim3 grid(T / 64, T, H);
        attn_kernel<<<grid, 256, smem_bytes>>>(proj, k1w, A2, spart);
    }

    // 5) rowinv
    {
        dim3 grid(T, H);
        rowinv_kernel<<<grid, 256>>>(spart, rinv);
    }

    // 6) z[q][h*64+e] = rinv[h,q] * sum_{p,c} A2[h][q][p*64+c] * Vq1[h][(p*64+c)][e]
    cudaMemsetAsync(z, 0, (size_t)T * H * DH * sizeof(float));
    launch_gemm(A2, A2H, 0, T * DH,
                vq1, HPJ, 0, DH,
                z, DH, 0, H * DH,
                T, DH, T * DH, 1, H, 0, nullptr, rinv, T, 4, 16);

    // 7) out = z @ W_out + b_out
    launch_gemm(z, 0, 0, H * DH, Wout, 0, 0, D,
                out, 0, 0, D,
                T, D, H * DH, 1, 1, 0, bout, nullptr, 0, 0, 1);
}

// round 9
// speedup vs baseline: 1.2865x; 1.2865x over previous
#include <cuda_runtime.h>
#include <cstdint>

// ---------------------------------------------------------------------------
// Problem constants: B=1, T=256, D=512, H=8, DH=64
// proj layout: [t, 5*512]; chunks k1@0, k2@512, q@1024, v1@1536, v2@2048.
// ---------------------------------------------------------------------------
#define T 256
#define D 512
#define H 8
#define DH 64
#define SST 66   // smem row stride (floats)

// Packed fp32x2 FMA (sm_100+)
#define FMA2(acc, a, b) asm("fma.rn.f32x2 %0, %1, %2, %0;" : "+l"(acc) : "l"(a), "l"(b))
#define DUP2(dst, f)    asm("mov.b64 %0, {%1, %1};" : "=l"(dst) : "r"(__float_as_uint(f)))
static __device__ __forceinline__ float lo2(unsigned long long v) { return __uint_as_float((unsigned int)v); }
static __device__ __forceinline__ float hi2(unsigned long long v) { return __uint_as_float((unsigned int)(v >> 32)); }

// 16x FFMA2 rank-1 update: acc[4][4] += apair[4] x bdup[4]
#define RANK1_FMA2(ACC, AR, B0, B1, B2, B3)                         \
    do {                                                            \
        unsigned long long _a0 = (AR)[0], _a1 = (AR)[1];            \
        unsigned long long _a2 = (AR)[2], _a3 = (AR)[3];            \
        FMA2(ACC[0][0], _a0, B0); FMA2(ACC[0][1], _a0, B1);         \
        FMA2(ACC[0][2], _a0, B2); FMA2(ACC[0][3], _a0, B3);         \
        FMA2(ACC[1][0], _a1, B0); FMA2(ACC[1][1], _a1, B1);         \
        FMA2(ACC[1][2], _a1, B2); FMA2(ACC[1][3], _a1, B3);         \
        FMA2(ACC[2][0], _a2, B0); FMA2(ACC[2][1], _a2, B1);         \
        FMA2(ACC[2][2], _a2, B2); FMA2(ACC[2][3], _a2, B3);         \
        FMA2(ACC[3][0], _a3, B0); FMA2(ACC[3][1], _a3, B1);         \
        FMA2(ACC[3][2], _a3, B2); FMA2(ACC[3][3], _a3, B3);         \
    } while (0)

// One 64-deep broadcast-FFMA2 GEMM mainloop over smem tiles A2d/B2d:
//   ACC[rowpair][col] += A2d[kk][ty*8 pairs] * B2d[kk][tx*4+j]
#define GEMM64(ACC, Abase, Bbase)                                            \
    do {                                                                     \
        _Pragma("unroll 16")                                                 \
        for (int kk = 0; kk < 64; kk++) {                                    \
            const unsigned long long* arow =                                 \
                reinterpret_cast<const unsigned long long*>(                 \
                    &(Abase)[kk * SST + ty * 8]);                            \
            unsigned long long b0, b1, b2, b3;                               \
            DUP2(b0, (Bbase)[kk * SST + tx * 4 + 0]);                        \
            DUP2(b1, (Bbase)[kk * SST + tx * 4 + 1]);                        \
            DUP2(b2, (Bbase)[kk * SST + tx * 4 + 2]);                        \
            DUP2(b3, (Bbase)[kk * SST + tx * 4 + 3]);                        \
            RANK1_FMA2(ACC, arow, b0, b1, b2, b3);                           \
        }                                                                    \
    } while (0)

// Scratch (device globals — allocation-free rule)
__device__ float g_proj[T * 5 * D];
__device__ float g_K1W[H * T * DH * DH];
__device__ float g_Vq1[H * T * DH * DH];
__device__ float g_spart[H * T * T];     // [h][p][q]
__device__ float g_rowinv[H * T];
__device__ float g_z[T * H * DH];        // [q][h*64+e], unscaled

// ---------------------------------------------------------------------------
// Generic batched tiled GEMM, 64x64 tile, 128 threads, 8x4/thread, FFMA2.
//   C[m,n] = sum_k A[m,k] * B(k,n); batch b -> h=b/P, p=b%P
//   transB: B indexed [n*ldb + k]
//   mode 5 (out proj): A-load scaled by rowscale[((k0+kk)>>6)*T + m]
//   ksplit>1: split-K with atomicAdd epilogue; rowscale: per-row scale.
// ---------------------------------------------------------------------------
__global__ __launch_bounds__(128)
void gemm_kernel(const float* __restrict__ A, const float* __restrict__ Bm,
                 float* __restrict__ C,
                 int lda, int ldb, int ldc,
                 int M, int N, int K, int P,
                 long long aH, long long aP,
                 long long bH, long long bP,
                 long long cH, long long cP,
                 int transB,
                 const float* __restrict__ bias,
                 const float* __restrict__ rowscale, int rsH,
                 int mode, int ksplit)
{
    int bz = blockIdx.z;
    int b  = bz / ksplit;
    int kc = bz % ksplit;
    int h = b / P, p = b % P;
    A  += (long long)h * aH + (long long)p * aP;
    Bm += (long long)h * bH + (long long)p * bP;
    C  += (long long)h * cH + (long long)p * cP;

    int m0 = blockIdx.y * 64;
    int n0 = blockIdx.x * 64;

    int k_begin = 0, k_end = K;
    if (ksplit > 1) { int kchunk = K / ksplit; k_begin = kc * kchunk; k_end = k_begin + kchunk; }

    __shared__ float As[64][SST];
    __shared__ float Bs[64][SST];

    int tid = threadIdx.x;
    int ty = tid >> 4, tx = tid & 15;

    unsigned long long acc2[4][4];
    #pragma unroll
    for (int i = 0; i < 4; i++)
        #pragma unroll
        for (int j = 0; j < 4; j++) acc2[i][j] = 0ULL;

    for (int k0 = k_begin; k0 < k_end; k0 += 64) {
        if (mode == 5) {
            #pragma unroll 8
            for (int i = tid; i < 4096; i += 128) {
                int r = i >> 6, kk = i & 63;
                int kg = k0 + kk, m = m0 + r;
                As[kk][r] = A[(long long)m * lda + kg] * rowscale[(kg >> 6) * T + m];
            }
        } else {
            #pragma unroll 8
            for (int i = tid; i < 4096; i += 128) {
                int r = i >> 6, kk = i & 63;
                As[kk][r] = A[(long long)(m0 + r) * lda + (k0 + kk)];
            }
        }
        if (transB) {
            #pragma unroll 8
            for (int i = tid; i < 4096; i += 128) {
                int n = i >> 6, kk = i & 63;
                Bs[kk][n] = Bm[(long long)(n0 + n) * ldb + (k0 + kk)];
            }
        } else {
            #pragma unroll 8
            for (int i = tid; i < 4096; i += 128) {
                int kk = i >> 6, n = i & 63;
                Bs[kk][n] = Bm[(long long)(k0 + kk) * ldb + (n0 + n)];
            }
        }
        __syncthreads();
        GEMM64(acc2, (&As[0][0]), (&Bs[0][0]));
        __syncthreads();
    }

    int n = n0 + tx * 4;
    float4 bv4 = {0,0,0,0};
    if (bias) { bv4.x = bias[n]; bv4.y = bias[n+1]; bv4.z = bias[n+2]; bv4.w = bias[n+3]; }
    #pragma unroll
    for (int ip = 0; ip < 4; ip++) {
        #pragma unroll
        for (int half = 0; half < 2; half++) {
            int m = m0 + ty * 8 + ip * 2 + half;
            float scale = (rowscale && mode != 5) ? rowscale[h * rsH + m] : 1.0f;
            float4 v;
            v.x = (half ? hi2(acc2[ip][0]) : lo2(acc2[ip][0])) * scale + bv4.x;
            v.y = (half ? hi2(acc2[ip][1]) : lo2(acc2[ip][1])) * scale + bv4.y;
            v.z = (half ? hi2(acc2[ip][2]) : lo2(acc2[ip][2])) * scale + bv4.z;
            v.w = (half ? hi2(acc2[ip][3]) : lo2(acc2[ip][3])) * scale + bv4.w;
            if (ksplit > 1) {
                atomicAdd(&C[(long long)m * ldc + n + 0], v.x);
                atomicAdd(&C[(long long)m * ldc + n + 1], v.y);
                atomicAdd(&C[(long long)m * ldc + n + 2], v.z);
                atomicAdd(&C[(long long)m * ldc + n + 3], v.w);
            } else {
                *reinterpret_cast<float4*>(&C[(long long)m * ldc + n]) = v;
            }
        }
    }
}

// ---------------------------------------------------------------------------
// Fully fused attention inner (round-6 broadcast microkernel + z fusion):
// per (h, p, qtile):
//   Phase1: St[j][q] = sum_i q_h[q,i] * K1W[h][p][j,i]        (smem As)
//   Per t-tile tt <= qt:
//     e[q][t] = (q>=p && t<=q) ? exp(logit/64) : 0            (regs -> Bs)
//     A2acc[q][c] += sum_t e[t][q] * v2[t][c]                 (regs)
//   GEMM3: zpart[q][e] = sum_c A2acc[c][q] * Vq1[h][p*64+c][e]
//   atomicAdd into z[q][h*64+e];  s_part[h][p][q] = row sums
// 3 smem buffers (Es aliases Bs) -> 50.7KB -> 4 blocks/SM.
// grid = (qt=4, p=256, h=8), block = 128.
// ---------------------------------------------------------------------------
__global__ __launch_bounds__(128)
void attn_kernel(const float* __restrict__ proj,
                 const float* __restrict__ k1w,
                 const float* __restrict__ vq1,
                 float* __restrict__ z,
                 float* __restrict__ s_part)
{
    int qt = blockIdx.x;
    int p  = blockIdx.y;
    int h  = blockIdx.z;
    if (qt * 64 + 63 < p) return;

    extern __shared__ float sm_dyn[];
    float* As = sm_dyn;                  // phase1 [i][q]; then St [j][q]
    float* Bs = sm_dyn + 64 * SST;       // K1W [i][j] / k2 [j][t] / Es [t][q] / A2t [c][q]
    float* Vs = sm_dyn + 2 * 64 * SST;   // v2 [t][c] / Vq1 [c][e]

    const float* qmat = proj + 2 * D + h * 64;           // [q][i], ld=5D
    const float* k2m  = proj + 1 * D + h * 64;           // [t][j], ld=5D
    const float* v2m  = proj + 4 * D + h * 64;           // [t][c], ld=5D
    const float* Bp   = k1w + ((long long)h * T + p) * (DH * DH);  // [j*64+i]
    const float* Vq   = vq1 + ((long long)h * T + p) * (DH * DH);  // [c*64+e]

    int tid = threadIdx.x;
    int ty = tid >> 4, tx = tid & 15;
    int q0 = qt * 64;

    // ---- Phase 1: St[q][j] = sum_i q[q,i] * K1W[j*64+i] ----
    unsigned long long st2[4][4];
    #pragma unroll
    for (int i = 0; i < 4; i++)
        #pragma unroll
        for (int j = 0; j < 4; j++) st2[i][j] = 0ULL;

    #pragma unroll 8
    for (int i = tid; i < 4096; i += 128) {
        int r = i >> 6, kk = i & 63;
        As[kk * SST + r] = qmat[(long long)(q0 + r) * (5 * D) + kk];
    }
    #pragma unroll 8
    for (int i = tid; i < 4096; i += 128) {
        int j = i >> 6, ii = i & 63;
        Bs[ii * SST + j] = Bp[i];
    }
    __syncthreads();

    GEMM64(st2, As, Bs);
    __syncthreads();                     // reads of As/Bs done

    // store St transposed into As: As[j][q]
    #pragma unroll
    for (int ip = 0; ip < 4; ip++)
        #pragma unroll
        for (int j = 0; j < 4; j++) {
            As[(tx * 4 + j) * SST + ty * 8 + ip * 2 + 0] = lo2(st2[ip][j]);
            As[(tx * 4 + j) * SST + ty * 8 + ip * 2 + 1] = hi2(st2[ip][j]);
        }

    float srow[8];
    #pragma unroll
    for (int r = 0; r < 8; r++) srow[r] = 0.0f;

    unsigned long long accA[4][4];       // A2 tile acc [qpair][c]
    #pragma unroll
    for (int i = 0; i < 4; i++)
        #pragma unroll
        for (int j = 0; j < 4; j++) accA[i][j] = 0ULL;

    // ---- Phase 2: t-tiles ----
    for (int tt = 0; tt <= qt; tt++) {
        int t0 = tt * 64;
        __syncthreads();   // prev GEMM2 done with Bs/Vs; St store visible (tt=0)

        #pragma unroll 8
        for (int i = tid; i < 4096; i += 128) {
            int t = i >> 6, jj = i & 63;
            Bs[jj * SST + t] = k2m[(long long)(t0 + t) * (5 * D) + jj];
        }
        #pragma unroll 8
        for (int i = tid; i < 4096; i += 128) {
            int t = i >> 6, c = i & 63;
            Vs[t * SST + c] = v2m[(long long)(t0 + t) * (5 * D) + c];
        }
        __syncthreads();

        // GEMM1: e = St^T x k2^T   (rows q, cols t, contract j)
        unsigned long long acc2[4][4];
        #pragma unroll
        for (int i = 0; i < 4; i++)
            #pragma unroll
            for (int j = 0; j < 4; j++) acc2[i][j] = 0ULL;
        GEMM64(acc2, As, Bs);
        __syncthreads();                 // all reads of Bs (k2) done

        // exp + mask -> Es[t][q] (aliased into Bs) + row sums
        bool diag = (tt == qt);
        #pragma unroll
        for (int ip = 0; ip < 4; ip++) {
            #pragma unroll
            for (int half = 0; half < 2; half++) {
                int r = ip * 2 + half;
                int q = q0 + ty * 8 + r;
                bool vrow = (q >= p);
                int tb = t0 + tx * 4;
                float x0 = half ? hi2(acc2[ip][0]) : lo2(acc2[ip][0]);
                float x1 = half ? hi2(acc2[ip][1]) : lo2(acc2[ip][1]);
                float x2 = half ? hi2(acc2[ip][2]) : lo2(acc2[ip][2]);
                float x3 = half ? hi2(acc2[ip][3]) : lo2(acc2[ip][3]);
                float e0 = (vrow && (!diag || tb + 0 <= q)) ? __expf(x0 * 0.015625f) : 0.0f;
                float e1 = (vrow && (!diag || tb + 1 <= q)) ? __expf(x1 * 0.015625f) : 0.0f;
                float e2 = (vrow && (!diag || tb + 2 <= q)) ? __expf(x2 * 0.015625f) : 0.0f;
                float e3 = (vrow && (!diag || tb + 3 <= q)) ? __expf(x3 * 0.015625f) : 0.0f;
                srow[r] += (e0 + e1) + (e2 + e3);
                int qc = ty * 8 + r;
                Bs[(tx * 4 + 0) * SST + qc] = e0;
                Bs[(tx * 4 + 1) * SST + qc] = e1;
                Bs[(tx * 4 + 2) * SST + qc] = e2;
                Bs[(tx * 4 + 3) * SST + qc] = e3;
            }
        }
        __syncthreads();

        // GEMM2: A2acc[q][c] += Es[t][q] * Vs[t][c]   (contract t)
        GEMM64(accA, Bs, Vs);
    }

    __syncthreads();                     // GEMM2 done reading Bs/Vs

    // ---- GEMM3: z contribution ----
    // store A2acc transposed into Bs: A2t[c][q]
    #pragma unroll
    for (int ip = 0; ip < 4; ip++)
        #pragma unroll
        for (int j = 0; j < 4; j++) {
            Bs[(tx * 4 + j) * SST + ty * 8 + ip * 2 + 0] = lo2(accA[ip][j]);
            Bs[(tx * 4 + j) * SST + ty * 8 + ip * 2 + 1] = hi2(accA[ip][j]);
        }
    // load Vq1 tile [c][e]
    #pragma unroll 8
    for (int i = tid; i < 4096; i += 128) {
        Vs[(i >> 6) * SST + (i & 63)] = Vq[i];
    }
    __syncthreads();

    unsigned long long zacc[4][4];
    #pragma unroll
    for (int i = 0; i < 4; i++)
        #pragma unroll
        for (int j = 0; j < 4; j++) zacc[i][j] = 0ULL;
    GEMM64(zacc, Bs, Vs);

    #pragma unroll
    for (int ip = 0; ip < 4; ip++) {
        #pragma unroll
        for (int half = 0; half < 2; half++) {
            int q = q0 + ty * 8 + ip * 2 + half;
            float* dst = &z[(long long)q * (H * DH) + h * 64 + tx * 4];
            atomicAdd(&dst[0], half ? hi2(zacc[ip][0]) : lo2(zacc[ip][0]));
            atomicAdd(&dst[1], half ? hi2(zacc[ip][1]) : lo2(zacc[ip][1]));
            atomicAdd(&dst[2], half ? hi2(zacc[ip][2]) : lo2(zacc[ip][2]));
            atomicAdd(&dst[3], half ? hi2(zacc[ip][3]) : lo2(zacc[ip][3]));
        }
    }

    // ---- s_part ----
    #pragma unroll
    for (int r = 0; r < 8; r++) {
        float s = srow[r];
        s += __shfl_xor_sync(0xffffffffu, s, 1);
        s += __shfl_xor_sync(0xffffffffu, s, 2);
        s += __shfl_xor_sync(0xffffffffu, s, 4);
        s += __shfl_xor_sync(0xffffffffu, s, 8);
        if (tx == 0)
            s_part[((long long)(h * T + p)) * T + q0 + ty * 8 + r] = s;
    }
}

// ---------------------------------------------------------------------------
// rowinv[h,q] = 1 / sum_{p<=q} s_part[h][p][q]
// ---------------------------------------------------------------------------
__global__ void rowinv_kernel(const float* __restrict__ s_part,
                              float* __restrict__ rowinv)
{
    int q = blockIdx.x, h = blockIdx.y;
    int tid = threadIdx.x;    // 256, tid == p
    float s = (tid <= q) ? s_part[((long long)(h * T + tid)) * T + q] : 0.0f;
    __shared__ float sh[256];
    sh[tid] = s;
    __syncthreads();
    for (int o = 128; o > 0; o >>= 1) {
        if (tid < o) sh[tid] += sh[tid + o];
        __syncthreads();
    }
    if (tid == 0) rowinv[h * T + q] = 1.0f / sh[0];
}

// ---------------------------------------------------------------------------
static inline void launch_gemm(const float* A, long long aH, long long aP, int lda,
                               const float* B, long long bH, long long bP, int ldb,
                               float* C, long long cH, long long cP, int ldc,
                               int M, int N, int K, int P, int batch,
                               int transB, const float* bias,
                               const float* rowscale, int rsH,
                               int mode, int ksplit)
{
    dim3 grid(N / 64, M / 64, batch * ksplit);
    gemm_kernel<<<grid, 128>>>(A, B, C, lda, ldb, ldc, M, N, K, P,
                               aH, aP, bH, bP, cH, cP,
                               transB, bias, rowscale, rsH, mode, ksplit);
}

extern "C" void kernel_launch(void* const* d_in, const int* in_sizes, int n_in,
                              void* d_out, int out_size)
{
    const float* x    = (const float*)d_in[0];
    const float* Wk   = (const float*)d_in[1];
    const float* bk   = (const float*)d_in[2];
    const float* WKq  = (const float*)d_in[3];
    const float* WVq  = (const float*)d_in[4];
    const float* Wout = (const float*)d_in[5];
    const float* bout = (const float*)d_in[6];
    float* out = (float*)d_out;

    float *proj, *k1w, *vq1, *spart, *rinv, *z;
    cudaGetSymbolAddress((void**)&proj,  g_proj);
    cudaGetSymbolAddress((void**)&k1w,   g_K1W);
    cudaGetSymbolAddress((void**)&vq1,   g_Vq1);
    cudaGetSymbolAddress((void**)&spart, g_spart);
    cudaGetSymbolAddress((void**)&rinv,  g_rowinv);
    cudaGetSymbolAddress((void**)&z,     g_z);

    const long long HPJ = (long long)T * DH * DH;

    // 1) proj = x @ W_kkqvv + b
    launch_gemm(x, 0, 0, D, Wk, 0, 0, 5 * D, proj, 0, 0, 5 * D,
                T, 5 * D, D, 1, 1, 0, bk, nullptr, 0, 0, 1);

    // 2) K1W[h] = k1_h @ W_Kq[h]
    launch_gemm(proj + 0, 64, 0, 5 * D, WKq, (long long)DH * DH * DH, 0, DH * DH,
                k1w, HPJ, 0, DH * DH,
                T, DH * DH, DH, 1, H, 0, nullptr, nullptr, 0, 0, 1);

    // 3) Vq1[h] = v1_h @ W_Vq[h]
    launch_gemm(proj + 3 * D, 64, 0, 5 * D, WVq, (long long)DH * DH * DH, 0, DH * DH,
                vq1, HPJ, 0, DH * DH,
                T, DH * DH, DH, 1, H, 0, nullptr, nullptr, 0, 0, 1);

    // 4) zero z, then fused attention inner (z via atomics) + partial sums
    cudaMemsetAsync(z, 0, (size_t)T * H * DH * sizeof(float));
    {
        int smem_bytes = 3 * 64 * SST * sizeof(float);   // 50688
        cudaFuncSetAttribute(attn_kernel,
                             cudaFuncAttributeMaxDynamicSharedMemorySize, smem_bytes);
        dim3 grid(T / 64, T, H);
        attn_kernel<<<grid, 128, smem_bytes>>>(proj, k1w, vq1, z, spart);
    }

    // 5) rowinv
    {
        dim3 grid(T, H);
        rowinv_kernel<<<grid, 256>>>(spart, rinv);
    }

    // 6) out = (z * rinv-per-(h,q)) @ W_out + b_out   (mode 5 scales A-loads)
    launch_gemm(z, 0, 0, H * DH, Wout, 0, 0, D,
                out, 0, 0, D,
                T, D, H * DH, 1, 1, 0, bout, rinv, 0, 5, 1);
}